// round 8
// baseline (speedup 1.0000x reference)
#include <cuda_runtime.h>
#include <cstdint>

// Problem constants
#define NV   128     // vocab
#define NN   512     // states
#define LL   4096    // tokens
#define GG   32      // CTAs (persistent, co-resident)
#define JC   16      // columns per CTA = NN/GG
#define TPB  256

// Per-CTA publish counters, each in its own 128B line (32 distinct L2 slices).
__device__ unsigned g_flag[GG * 32];
// Vector double buffer, spread: quad q (4 floats) lives at [q*64], 256B stride
// -> 32KB span -> many slice-hash combos -> no LTS hotspot on the bulk read.
__device__ float g_dataP[2][128 * 64];
__device__ float g_pdot[LL * GG];

__device__ __forceinline__ unsigned ld_acq(const unsigned* p) {
    unsigned v;
    asm volatile("ld.acquire.gpu.global.u32 %0, [%1];" : "=r"(v) : "l"(p));
    return v;
}
__device__ __forceinline__ void st_rel(unsigned* p, unsigned v) {
    asm volatile("st.release.gpu.global.u32 [%0], %1;" :: "l"(p), "r"(v));
}
__device__ __forceinline__ void st_cg(float* p, float v) {
    asm volatile("st.global.cg.f32 [%0], %1;" :: "l"(p), "f"(v));
}
__device__ __forceinline__ float4 ld_cg4(const float* p) {
    float4 v;
    asm volatile("ld.global.cg.v4.f32 {%0,%1,%2,%3}, [%4];"
                 : "=f"(v.x), "=f"(v.y), "=f"(v.z), "=f"(v.w) : "l"(p));
    return v;
}

// Reset flags + seed u_0 = start (parity 0). Runs before walk each launch so
// graph replays start from a clean monotonic-counter state.
__global__ void init_kernel(const float* __restrict__ start) {
    int j = threadIdx.x;
    if (j < GG) g_flag[j * 32] = 0u;
    if (j < NN) {
        int q = j >> 2, e = j & 3;
        g_dataP[0][q * 64 + e] = start[j];
    }
}

__global__ void __launch_bounds__(TPB, 1)
walk_kernel(const int* __restrict__ tokens,
            const float* __restrict__ transfer,
            const float* __restrict__ probs) {
    __shared__ float uvec[NN];    // full u_{t-1}
    __shared__ float red[128];    // 8 warps x 16 cols
    __shared__ int   stok[LL];

    const int tid = threadIdx.x;
    const int g   = blockIdx.x;
    const int j0  = g * JC;
    const int lane = tid & 31, wid = tid >> 5;
    const int qd = tid & 3, r0 = tid >> 2;   // col-quad, row-group

    for (int i = tid; i < LL; i += TPB) stok[i] = tokens[i];
    __syncthreads();

    // Matrix slice register double-buffer: 8 float4 per thread per step.
    float4 A[8], B[8];
    {
        const int tok = stok[0];
        const float* b = transfer + (size_t)tok * (NN * NN) + j0 + 4 * qd;
        #pragma unroll
        for (int k = 0; k < 8; ++k)
            A[k] = *reinterpret_cast<const float4*>(b + (size_t)(r0 + 64 * k) * NN);
    }

    auto body = [&](int t, float4* cur, float4* nxt) {
        // ---- prefetch next matrix + emission probs (token-known, long flight)
        float pv = 0.f;
        if (t < LL) {
            const int tok2 = stok[t];
            const float* b = transfer + (size_t)tok2 * (NN * NN) + j0 + 4 * qd;
            #pragma unroll
            for (int k = 0; k < 8; ++k)
                nxt[k] = *reinterpret_cast<const float4*>(b + (size_t)(r0 + 64 * k) * NN);
            if (wid == 1 && lane < JC)
                pv = __ldg(&probs[(size_t)tok2 * NN + j0 + lane]);
        }

        // ---- detection: warp 0 polls 32 per-CTA flags (2-deep pipeline)
        if (wid == 0) {
            const unsigned want = (unsigned)(t - 1);
            const unsigned* fp = &g_flag[lane * 32];
            unsigned a = ld_acq(fp);
            unsigned b2 = ld_acq(fp);
            for (;;) {
                if (__all_sync(0xffffffffu, a >= want)) break;
                a = b2;
                b2 = ld_acq(fp);
            }
        }
        __syncthreads();   // flag acquire in warp0 orders the .cg loads below

        // ---- bulk read u_{t-1}: one float4 per thread over a spread layout
        {
            const int par = (t - 1) & 1;
            if (tid < 128) {
                float4 v = ld_cg4(&g_dataP[par][tid * 64]);
                *reinterpret_cast<float4*>(&uvec[tid * 4]) = v;
            }
        }
        __syncthreads();

        // ---- GEMV slice from registers: out[j0+c] = sum_i u[i] * T[i][j0+c]
        float4 acc = make_float4(0.f, 0.f, 0.f, 0.f);
        #pragma unroll
        for (int k = 0; k < 8; ++k) {
            float u = uvec[r0 + (k << 6)];
            acc.x = fmaf(u, cur[k].x, acc.x); acc.y = fmaf(u, cur[k].y, acc.y);
            acc.z = fmaf(u, cur[k].z, acc.z); acc.w = fmaf(u, cur[k].w, acc.w);
        }
        #pragma unroll
        for (int d = 4; d < 32; d <<= 1) {
            acc.x += __shfl_xor_sync(0xffffffffu, acc.x, d);
            acc.y += __shfl_xor_sync(0xffffffffu, acc.y, d);
            acc.z += __shfl_xor_sync(0xffffffffu, acc.z, d);
            acc.w += __shfl_xor_sync(0xffffffffu, acc.w, d);
        }
        if (lane < 4)
            *reinterpret_cast<float4*>(red + wid * 16 + lane * 4) = acc;
        __syncthreads();

        // ---- warp 0: gather + publish + flag. warp 1: gather + emission.
        if (tid < JC) {
            float v = 0.f;
            #pragma unroll
            for (int w = 0; w < 8; ++w) v += red[w * 16 + tid];
            const int j = j0 + tid;                 // global column
            const int par = t & 1;
            st_cg(&g_dataP[par][(j >> 2) * 64 + (j & 3)], v);
            __syncwarp(0x0000ffffu);
            if (tid == 0) st_rel(&g_flag[g * 32], (unsigned)t);
        } else if (wid == 1 && lane < JC) {
            float v = 0.f;
            #pragma unroll
            for (int w = 0; w < 8; ++w) v += red[w * 16 + lane];
            if (t < LL) {
                float pp = v * pv;
                #pragma unroll
                for (int d = 1; d < JC; d <<= 1)
                    pp += __shfl_xor_sync(0x0000FFFFu, pp, d);
                if (lane == 0) g_pdot[t * GG + g] = pp;
            }
        }
    };

    #pragma unroll 1
    for (int t = 1; t <= LL; t += 2) {   // LL even
        body(t,     A, B);
        body(t + 1, B, A);
    }
}

__global__ void finalize_kernel(const int* __restrict__ tokens,
                                const float* __restrict__ start,
                                const float* __restrict__ probs,
                                const float* __restrict__ finals,
                                float* __restrict__ out, int out_size) {
    __shared__ double sd[TPB];
    const int tid = threadIdx.x;

    // emission 0: dot(start, probs[tok_0]) — walk covers t=1..LL-1
    {
        const int tok0 = tokens[0];
        double e = 0.0;
        for (int j = tid; j < NN; j += TPB)
            e += (double)start[j] * (double)probs[(size_t)tok0 * NN + j];
        sd[tid] = e; __syncthreads();
        for (int d = TPB / 2; d > 0; d >>= 1) {
            if (tid < d) sd[tid] += sd[tid + d];
            __syncthreads();
        }
    }
    double e0 = sd[0];
    __syncthreads();

    // prob factors: d_t = sum_g pdot[t][g], t=1..LL-1; product in double
    double lp = (tid == 0) ? e0 : 1.0;
    for (int t = tid; t < LL; t += TPB) {
        if (t == 0) continue;
        float s = 0.f;
        #pragma unroll
        for (int g2 = 0; g2 < GG; ++g2) s += g_pdot[t * GG + g2];
        lp *= (double)s;
    }
    sd[tid] = lp; __syncthreads();
    for (int d = TPB / 2; d > 0; d >>= 1) {
        if (tid < d) sd[tid] *= sd[tid + d];
        __syncthreads();
    }
    double totprod = sd[0];
    __syncthreads();

    // final u (LL even -> parity 0), finals dot, write outputs
    double fp = 0.0;
    for (int j = tid; j < NN; j += TPB) {
        float uv = g_dataP[0][(j >> 2) * 64 + (j & 3)];
        if (j < out_size) out[j] = uv;
        fp += (double)uv * (double)finals[j];
    }
    sd[tid] = fp; __syncthreads();
    for (int d = TPB / 2; d > 0; d >>= 1) {
        if (tid < d) sd[tid] += sd[tid + d];
        __syncthreads();
    }
    if (tid == 0 && out_size > NN) out[NN] = (float)(totprod * sd[0]);
}

extern "C" void kernel_launch(void* const* d_in, const int* in_sizes, int n_in,
                              void* d_out, int out_size) {
    const int*   tokens   = (const int*)d_in[0];
    const float* start    = (const float*)d_in[1];
    const float* transfer = (const float*)d_in[2];
    const float* probs    = (const float*)d_in[3];
    const float* finals   = (const float*)d_in[4];
    float* out = (float*)d_out;

    init_kernel<<<1, 512>>>(start);
    walk_kernel<<<GG, TPB>>>(tokens, transfer, probs);
    finalize_kernel<<<1, TPB>>>(tokens, start, probs, finals, out, out_size);
}

// round 10
// speedup vs baseline: 1.8726x; 1.8726x over previous
#include <cuda_runtime.h>
#include <cstdint>

// Problem constants
#define NV   128     // vocab
#define NN   512     // states
#define LL   4096    // tokens
#define GG   32      // CTAs (persistent, co-resident)
#define JC   16      // columns per CTA = NN/GG
#define TPB  256

// Tagged vector buffers: high 32 bits = step tag, low 32 = float bits.
__device__ unsigned long long g_u[2][NN];
__device__ float g_pdot[LL * GG];
// Repacked transfer: g_tx[(v*GG+g)] = contiguous [512 rows x 16 cols] slice
// (chunk c = row*4 + colquad, 16B each). 128 MB static.
__device__ float g_tx[(size_t)NV * GG * NN * JC];

// L2-coherent GPU-scope accesses (8B word fuses tag+data: no fence needed).
__device__ __forceinline__ unsigned long long ld_poll(const unsigned long long* p) {
    unsigned long long v;
    asm volatile("ld.relaxed.gpu.global.b64 %0, [%1];" : "=l"(v) : "l"(p));
    return v;
}
__device__ __forceinline__ void st_pub(unsigned long long* p, unsigned long long v) {
    asm volatile("st.relaxed.gpu.global.b64 [%0], %1;" :: "l"(p), "l"(v));
}

// Reset tags + seed u_0 = start. Runs before walk each launch (kills stale
// tags from the previous graph replay — ABA hazard otherwise).
__global__ void init_kernel(const float* __restrict__ start) {
    int j = threadIdx.x;
    if (j < NN) {
        st_pub(&g_u[1][j], 0xFFFFFFFF00000000ull);
        unsigned long long v = (unsigned long long)__float_as_uint(start[j]); // tag 0
        st_pub(&g_u[0][j], v);
    }
}

// Repack transfer -> g_tx. CTA (v,g): strided 64B reads, contiguous 32KB write.
__global__ void transform_kernel(const float* __restrict__ transfer) {
    const int v  = blockIdx.x >> 5;
    const int g  = blockIdx.x & 31;
    const int tid = threadIdx.x;
    const int qd = tid & 3, r0 = tid >> 2;
    const float* src = transfer + (size_t)v * (NN * NN) + g * JC + 4 * qd;
    float* dst = g_tx + (size_t)blockIdx.x * (NN * JC);
    #pragma unroll
    for (int k = 0; k < 8; ++k) {
        const int row = r0 + 64 * k;
        float4 val = *reinterpret_cast<const float4*>(src + (size_t)row * NN);
        *reinterpret_cast<float4*>(dst + row * JC + 4 * qd) = val;
    }
}

__global__ void __launch_bounds__(TPB, 1)
walk_kernel(const int* __restrict__ tokens,
            const float* __restrict__ probs) {
    __shared__ float uvec[NN];    // full u_{t-1}
    __shared__ float red[128];    // 8 warps x 16 cols
    __shared__ int   stok[LL];

    const int tid = threadIdx.x;
    const int g   = blockIdx.x;
    const int j0  = g * JC;
    const int lane = tid & 31, wid = tid >> 5;
    const int qd = tid & 3, r0 = tid >> 2;   // col-quad, row-group

    for (int i = tid; i < LL; i += TPB) stok[i] = tokens[i];
    __syncthreads();

    // Matrix slice register double-buffer: 8 float4 per thread per step.
    // Coalesced: thread tid owns chunks tid + 256k of the contiguous slice.
    float4 A[8], B[8];
    {
        const float* b = g_tx + (size_t)(stok[0] * GG + g) * (NN * JC) + 4 * tid;
        #pragma unroll
        for (int k = 0; k < 8; ++k)
            A[k] = *reinterpret_cast<const float4*>(b + k * (4 * TPB));
    }

    auto body = [&](int t, float4* cur, float4* nxt) {
        // ---- poll u_{t-1} FIRST (L1tex queue is clean: prefetch from the
        //      previous step drained during its GEMV/reduce)
        {
            const unsigned wantTag = (unsigned)(t - 1);
            const int par = (t - 1) & 1;
            const unsigned long long* p0 = &g_u[par][tid];
            const unsigned long long* p1 = &g_u[par][tid + TPB];
            unsigned long long a0 = ld_poll(p0), a1 = ld_poll(p1);
            unsigned long long b0 = ld_poll(p0), b1 = ld_poll(p1);
            unsigned long long c0 = ld_poll(p0), c1 = ld_poll(p1);
            unsigned long long v0, v1;
            for (;;) {
                if ((unsigned)(a0 >> 32) == wantTag && (unsigned)(a1 >> 32) == wantTag) {
                    v0 = a0; v1 = a1; break;
                }
                a0 = ld_poll(p0); a1 = ld_poll(p1);
                if ((unsigned)(b0 >> 32) == wantTag && (unsigned)(b1 >> 32) == wantTag) {
                    v0 = b0; v1 = b1; break;
                }
                b0 = ld_poll(p0); b1 = ld_poll(p1);
                if ((unsigned)(c0 >> 32) == wantTag && (unsigned)(c1 >> 32) == wantTag) {
                    v0 = c0; v1 = c1; break;
                }
                c0 = ld_poll(p0); c1 = ld_poll(p1);
            }
            uvec[tid]       = __uint_as_float((unsigned)v0);
            uvec[tid + TPB] = __uint_as_float((unsigned)v1);
        }

        // ---- prefetch step t+1 matrix (coalesced, 256 wf) + emission probs.
        //      Issued after the poll; drains during GEMV below.
        float pv = 0.f;
        if (t < LL) {
            const int tok2 = stok[t];
            const float* b = g_tx + (size_t)(tok2 * GG + g) * (NN * JC) + 4 * tid;
            #pragma unroll
            for (int k = 0; k < 8; ++k)
                nxt[k] = *reinterpret_cast<const float4*>(b + k * (4 * TPB));
            if (wid == 1 && lane < JC)
                pv = __ldg(&probs[(size_t)tok2 * NN + j0 + lane]);
        }
        __syncthreads();   // uvec visible to all

        // ---- GEMV slice from registers: out[j0+c] = sum_i u[i] * T[i][j0+c]
        float4 acc = make_float4(0.f, 0.f, 0.f, 0.f);
        #pragma unroll
        for (int k = 0; k < 8; ++k) {
            float u = uvec[r0 + (k << 6)];
            acc.x = fmaf(u, cur[k].x, acc.x); acc.y = fmaf(u, cur[k].y, acc.y);
            acc.z = fmaf(u, cur[k].z, acc.z); acc.w = fmaf(u, cur[k].w, acc.w);
        }
        #pragma unroll
        for (int d = 4; d < 32; d <<= 1) {
            acc.x += __shfl_xor_sync(0xffffffffu, acc.x, d);
            acc.y += __shfl_xor_sync(0xffffffffu, acc.y, d);
            acc.z += __shfl_xor_sync(0xffffffffu, acc.z, d);
            acc.w += __shfl_xor_sync(0xffffffffu, acc.w, d);
        }
        if (lane < 4)
            *reinterpret_cast<float4*>(red + wid * 16 + lane * 4) = acc;
        __syncthreads();

        // ---- warp 0: gather + publish (fused tag+data). warp 1: emission.
        if (tid < JC) {
            float v = 0.f;
            #pragma unroll
            for (int w = 0; w < 8; ++w) v += red[w * 16 + tid];
            unsigned long long pvw =
                ((unsigned long long)(unsigned)t << 32) |
                (unsigned long long)__float_as_uint(v);
            st_pub(&g_u[t & 1][j0 + tid], pvw);
        } else if (wid == 1 && lane < JC) {
            float v = 0.f;
            #pragma unroll
            for (int w = 0; w < 8; ++w) v += red[w * 16 + lane];
            if (t < LL) {
                float pp = v * pv;
                #pragma unroll
                for (int d = 1; d < JC; d <<= 1)
                    pp += __shfl_xor_sync(0x0000FFFFu, pp, d);
                if (lane == 0) g_pdot[t * GG + g] = pp;
            }
        }
    };

    #pragma unroll 1
    for (int t = 1; t <= LL; t += 2) {   // LL even
        body(t,     A, B);
        body(t + 1, B, A);
    }
}

__global__ void finalize_kernel(const int* __restrict__ tokens,
                                const float* __restrict__ start,
                                const float* __restrict__ probs,
                                const float* __restrict__ finals,
                                float* __restrict__ out, int out_size) {
    __shared__ double sd[TPB];
    const int tid = threadIdx.x;

    // emission 0: dot(start, probs[tok_0]) — walk covers t=1..LL-1
    {
        const int tok0 = tokens[0];
        double e = 0.0;
        for (int j = tid; j < NN; j += TPB)
            e += (double)start[j] * (double)probs[(size_t)tok0 * NN + j];
        sd[tid] = e; __syncthreads();
        for (int d = TPB / 2; d > 0; d >>= 1) {
            if (tid < d) sd[tid] += sd[tid + d];
            __syncthreads();
        }
    }
    double e0 = sd[0];
    __syncthreads();

    // prob factors: d_t = sum_g pdot[t][g], t=1..LL-1; product in double
    double lp = (tid == 0) ? e0 : 1.0;
    for (int t = tid; t < LL; t += TPB) {
        if (t == 0) continue;
        float s = 0.f;
        #pragma unroll
        for (int g2 = 0; g2 < GG; ++g2) s += g_pdot[t * GG + g2];
        lp *= (double)s;
    }
    sd[tid] = lp; __syncthreads();
    for (int d = TPB / 2; d > 0; d >>= 1) {
        if (tid < d) sd[tid] *= sd[tid + d];
        __syncthreads();
    }
    double totprod = sd[0];
    __syncthreads();

    // final u (LL even -> parity 0), finals dot, write outputs
    double fp = 0.0;
    for (int j = tid; j < NN; j += TPB) {
        unsigned long long v = g_u[0][j];
        float uv = __uint_as_float((unsigned)v);
        if (j < out_size) out[j] = uv;
        fp += (double)uv * (double)finals[j];
    }
    sd[tid] = fp; __syncthreads();
    for (int d = TPB / 2; d > 0; d >>= 1) {
        if (tid < d) sd[tid] += sd[tid + d];
        __syncthreads();
    }
    if (tid == 0 && out_size > NN) out[NN] = (float)(totprod * sd[0]);
}

extern "C" void kernel_launch(void* const* d_in, const int* in_sizes, int n_in,
                              void* d_out, int out_size) {
    const int*   tokens   = (const int*)d_in[0];
    const float* start    = (const float*)d_in[1];
    const float* transfer = (const float*)d_in[2];
    const float* probs    = (const float*)d_in[3];
    const float* finals   = (const float*)d_in[4];
    float* out = (float*)d_out;

    init_kernel<<<1, 512>>>(start);
    transform_kernel<<<NV * GG, TPB>>>(transfer);
    walk_kernel<<<GG, TPB>>>(tokens, probs);
    finalize_kernel<<<1, TPB>>>(tokens, start, probs, finals, out, out_size);
}